// round 4
// baseline (speedup 1.0000x reference)
#include <cuda_runtime.h>

#define NBLK 296              // 148 SMs x 2 resident CTAs (guaranteed by launch_bounds)

// Scratch (no allocations allowed). All state is either overwritten each run,
// wraps (g_count), or is monotonic with entry-captured baseline (g_epoch) ->
// deterministic + graph-replay safe.
__device__ double                g_partials[NBLK];
__device__ float                 g_total;
__device__ unsigned int          g_count;
__device__ volatile unsigned int g_epoch;

__global__ void __launch_bounds__(256, 2) fused_kernel(const float4* __restrict__ x4,
                                                       float4* __restrict__ out4,
                                                       long long n4)
{
    const long long tid    = (long long)blockIdx.x * blockDim.x + threadIdx.x;
    const long long stride = (long long)gridDim.x * blockDim.x;

    // Capture epoch BEFORE doing any work: the bumper can only fire after
    // every CTA (including this one) has arrived, so this read is race-free.
    const unsigned epoch0 = g_epoch;

    // ---------------- Phase 1: reduction, 8 independent float4 streams ------
    float s0=0.f,s1=0.f,s2=0.f,s3=0.f,s4=0.f,s5=0.f,s6=0.f,s7=0.f;
    float t0=0.f,t1=0.f,t2=0.f,t3=0.f;   // lane accumulators folded per stream

    long long i = tid;
    for (; i + 7*stride < n4; i += 8*stride) {
        float4 v0 = x4[i];
        float4 v1 = x4[i +   stride];
        float4 v2 = x4[i + 2*stride];
        float4 v3 = x4[i + 3*stride];
        float4 v4 = x4[i + 4*stride];
        float4 v5 = x4[i + 5*stride];
        float4 v6 = x4[i + 6*stride];
        float4 v7 = x4[i + 7*stride];
        s0 += (v0.x + v0.y) + (v0.z + v0.w);
        s1 += (v1.x + v1.y) + (v1.z + v1.w);
        s2 += (v2.x + v2.y) + (v2.z + v2.w);
        s3 += (v3.x + v3.y) + (v3.z + v3.w);
        s4 += (v4.x + v4.y) + (v4.z + v4.w);
        s5 += (v5.x + v5.y) + (v5.z + v5.w);
        s6 += (v6.x + v6.y) + (v6.z + v6.w);
        s7 += (v7.x + v7.y) + (v7.z + v7.w);
    }
    for (; i < n4; i += stride) {
        float4 v = x4[i];
        t0 += v.x; t1 += v.y; t2 += v.z; t3 += v.w;
    }

    double acc = ((double)s0 + (double)s1) + ((double)s2 + (double)s3)
               + ((double)s4 + (double)s5) + ((double)s6 + (double)s7)
               + ((double)t0 + (double)t1) + ((double)t2 + (double)t3);

    __shared__ double sdata[256];
    sdata[threadIdx.x] = acc;
    __syncthreads();
    for (int s = 128; s > 0; s >>= 1) {
        if (threadIdx.x < s) sdata[threadIdx.x] += sdata[threadIdx.x + s];
        __syncthreads();
    }

    // ---------------- Arrival + last-block finalize -------------------------
    __shared__ bool s_isLast;
    if (threadIdx.x == 0) {
        g_partials[blockIdx.x] = sdata[0];
        __threadfence();
        unsigned v = atomicInc(&g_count, gridDim.x - 1);   // wraps -> replay-safe
        s_isLast = (v == gridDim.x - 1);
    }
    __syncthreads();

    if (s_isLast) {
        double facc = 0.0;
        for (int k = threadIdx.x; k < NBLK; k += 256) facc += g_partials[k];
        sdata[threadIdx.x] = facc;
        __syncthreads();
        for (int s = 128; s > 0; s >>= 1) {
            if (threadIdx.x < s) sdata[threadIdx.x] += sdata[threadIdx.x + s];
            __syncthreads();
        }
        if (threadIdx.x == 0) {
            float  sf = (float)sdata[0];        // mimic jnp.sum's fp32 result
            double nn = trunc((double)sf);
            double tt = (nn > 1.0) ? nn * (nn - 1.0) * 0.5 : 0.0;
            g_total = (float)tt;
            __threadfence();
            g_epoch = g_epoch + 1;              // release the other CTAs
        }
        __syncthreads();
    } else {
        if (threadIdx.x == 0) {
            while (g_epoch == epoch0) { __nanosleep(64); }
            __threadfence();                    // order g_total read after flag
        }
        __syncthreads();
    }

    __shared__ float s_t;
    if (threadIdx.x == 0) s_t = g_total;
    __syncthreads();
    const float t = s_t;

    // ---------------- Phase 2: out = x + t, streaming ------------------------
    long long j = tid;
    for (; j + 3*stride < n4; j += 4*stride) {
        float4 a = __ldcs(&x4[j]);
        float4 b = __ldcs(&x4[j +   stride]);
        float4 c = __ldcs(&x4[j + 2*stride]);
        float4 d = __ldcs(&x4[j + 3*stride]);
        a.x += t; a.y += t; a.z += t; a.w += t;
        b.x += t; b.y += t; b.z += t; b.w += t;
        c.x += t; c.y += t; c.z += t; c.w += t;
        d.x += t; d.y += t; d.z += t; d.w += t;
        __stcs(&out4[j],            a);
        __stcs(&out4[j +   stride], b);
        __stcs(&out4[j + 2*stride], c);
        __stcs(&out4[j + 3*stride], d);
    }
    for (; j < n4; j += stride) {
        float4 a = __ldcs(&x4[j]);
        a.x += t; a.y += t; a.z += t; a.w += t;
        __stcs(&out4[j], a);
    }
}

extern "C" void kernel_launch(void* const* d_in, const int* in_sizes, int n_in,
                              void* d_out, int out_size)
{
    const float4* x4   = (const float4*)d_in[0];
    float4*       out4 = (float4*)d_out;
    long long n  = (long long)in_sizes[0];   // 8192*8192
    long long n4 = n >> 2;

    fused_kernel<<<NBLK, 256>>>(x4, out4, n4);
}

// round 5
// speedup vs baseline: 1.0569x; 1.0569x over previous
#include <cuda_runtime.h>

#define NBLK    296            // 148 SMs x 2 resident CTAs
#define NTHR    512            // 1024 threads/SM -> 32 warps/SM (~50% occ)

// Scratch (no allocations). State overwritten each run, wraps (g_count), or is
// monotonic with entry-captured baseline (g_epoch) -> graph-replay safe.
__device__ double                g_partials[NBLK];
__device__ float                 g_total;
__device__ unsigned int          g_count;
__device__ volatile unsigned int g_epoch;

__global__ void __launch_bounds__(NTHR, 2) fused_kernel(const float4* __restrict__ x4,
                                                        float4* __restrict__ out4,
                                                        long long n4)
{
    const long long tid    = (long long)blockIdx.x * blockDim.x + threadIdx.x;
    const long long stride = (long long)gridDim.x * blockDim.x;

    // Capture epoch BEFORE any work: bumper fires only after all CTAs arrive.
    const unsigned epoch0 = g_epoch;

    // -------- Phase 1: ascending reduction, 4 independent float4 streams ----
    float s0=0.f, s1=0.f, s2=0.f, s3=0.f;

    long long i = tid;
    for (; i + 3*stride < n4; i += 4*stride) {
        float4 v0 = x4[i];
        float4 v1 = x4[i +   stride];
        float4 v2 = x4[i + 2*stride];
        float4 v3 = x4[i + 3*stride];
        s0 += (v0.x + v0.y) + (v0.z + v0.w);
        s1 += (v1.x + v1.y) + (v1.z + v1.w);
        s2 += (v2.x + v2.y) + (v2.z + v2.w);
        s3 += (v3.x + v3.y) + (v3.z + v3.w);
    }
    for (; i < n4; i += stride) {
        float4 v = x4[i];
        s0 += (v.x + v.y) + (v.z + v.w);
    }

    double acc = ((double)s0 + (double)s1) + ((double)s2 + (double)s3);

    __shared__ double sdata[NTHR];
    sdata[threadIdx.x] = acc;
    __syncthreads();
    for (int s = NTHR/2; s > 0; s >>= 1) {
        if (threadIdx.x < s) sdata[threadIdx.x] += sdata[threadIdx.x + s];
        __syncthreads();
    }

    // -------- Arrival + last-block finalize ---------------------------------
    __shared__ bool s_isLast;
    if (threadIdx.x == 0) {
        g_partials[blockIdx.x] = sdata[0];
        __threadfence();
        unsigned v = atomicInc(&g_count, gridDim.x - 1);   // wraps -> replay-safe
        s_isLast = (v == gridDim.x - 1);
    }
    __syncthreads();

    if (s_isLast) {
        double facc = 0.0;
        for (int k = threadIdx.x; k < NBLK; k += NTHR) facc += g_partials[k];
        sdata[threadIdx.x] = facc;
        __syncthreads();
        for (int s = NTHR/2; s > 0; s >>= 1) {
            if (threadIdx.x < s) sdata[threadIdx.x] += sdata[threadIdx.x + s];
            __syncthreads();
        }
        if (threadIdx.x == 0) {
            float  sf = (float)sdata[0];        // mimic jnp.sum's fp32 result
            double nn = trunc((double)sf);
            double tt = (nn > 1.0) ? nn * (nn - 1.0) * 0.5 : 0.0;
            g_total = (float)tt;
            __threadfence();
            g_epoch = g_epoch + 1;              // release
        }
        __syncthreads();
    } else {
        if (threadIdx.x == 0) {
            while (g_epoch == epoch0) { __nanosleep(64); }
            __threadfence();
        }
        __syncthreads();
    }

    __shared__ float s_t;
    if (threadIdx.x == 0) s_t = g_total;
    __syncthreads();
    const float t = s_t;

    // -------- Phase 2: out = x + t, DESCENDING over this thread's own
    //          phase-1 index set, so the first reads hit the L2 lines this
    //          SM pulled at the end of phase 1. __stcs keeps writes from
    //          evicting the residue; __ldcs avoids read pollution. ---------
    long long iters = (n4 - 1 - tid) / stride + 1;     // tid < n4 always here
    long long j = tid + (iters - 1) * stride;

    for (; iters >= 4; iters -= 4, j -= 4*stride) {
        float4 a = __ldcs(&x4[j]);
        float4 b = __ldcs(&x4[j -   stride]);
        float4 c = __ldcs(&x4[j - 2*stride]);
        float4 d = __ldcs(&x4[j - 3*stride]);
        a.x += t; a.y += t; a.z += t; a.w += t;
        b.x += t; b.y += t; b.z += t; b.w += t;
        c.x += t; c.y += t; c.z += t; c.w += t;
        d.x += t; d.y += t; d.z += t; d.w += t;
        __stcs(&out4[j],            a);
        __stcs(&out4[j -   stride], b);
        __stcs(&out4[j - 2*stride], c);
        __stcs(&out4[j - 3*stride], d);
    }
    for (; iters > 0; iters--, j -= stride) {
        float4 a = __ldcs(&x4[j]);
        a.x += t; a.y += t; a.z += t; a.w += t;
        __stcs(&out4[j], a);
    }
}

extern "C" void kernel_launch(void* const* d_in, const int* in_sizes, int n_in,
                              void* d_out, int out_size)
{
    const float4* x4   = (const float4*)d_in[0];
    float4*       out4 = (float4*)d_out;
    long long n  = (long long)in_sizes[0];   // 8192*8192
    long long n4 = n >> 2;

    fused_kernel<<<NBLK, NTHR>>>(x4, out4, n4);
}